// round 1
// baseline (speedup 1.0000x reference)
#include <cuda_runtime.h>
#include <math.h>

#define NROWS 65536
#define D 512
#define H 10
#define G4 40

// ---------------- scratch (static device globals; no allocation) ----------------
__device__ float  g_y[NROWS * H];        // layer-1 pre-BN activations
__device__ float  g_u[NROWS * G4];       // precomputed input-gate bases
__device__ float  g_outs[NROWS * H];     // scan outputs (ht)
__device__ int    g_meta[NROWS];         // zp | (bnd<<8)
__device__ double g_s1[H], g_sq1[H];     // BN1 sums (atomically accumulated)
__device__ float  g_scale1[H], g_shift1[H];
__device__ float  g_bias0[G4];           // b_ih + b_hh (zero-input cell base)
__device__ double g_s2[2 * H];           // BN2 sums written by scan
__device__ float  g_alpha[H];
__device__ float  g_cst[1];

// ---------------- init: zero the atomically-accumulated stats ----------------
__global__ void k_init() {
    int t = threadIdx.x;
    if (t < H) { g_s1[t] = 0.0; g_sq1[t] = 0.0; }
}

// ---------------- kernel A: y = x @ W1^T + b1, accumulate BN1 sums ----------------
// one warp per row, float4 loads
__global__ void k_proj(const float* __restrict__ x,
                       const float* __restrict__ W1,
                       const float* __restrict__ b1) {
    int gtid  = blockIdx.x * blockDim.x + threadIdx.x;
    int w     = gtid >> 5;
    int lane  = threadIdx.x & 31;
    int nwarp = (gridDim.x * blockDim.x) >> 5;

    double ls[H], lq[H];
#pragma unroll
    for (int j = 0; j < H; j++) { ls[j] = 0.0; lq[j] = 0.0; }

    const float4* x4  = reinterpret_cast<const float4*>(x);
    const float4* W14 = reinterpret_cast<const float4*>(W1);

    for (int n = w; n < NROWS; n += nwarp) {
        float acc[H];
#pragma unroll
        for (int j = 0; j < H; j++) acc[j] = 0.f;
        const float4* xr = x4 + (size_t)n * (D / 4);
#pragma unroll
        for (int it = 0; it < D / 4 / 32; it++) {
            float4 xv = __ldg(xr + lane + 32 * it);
#pragma unroll
            for (int j = 0; j < H; j++) {
                float4 wv = __ldg(W14 + j * (D / 4) + lane + 32 * it);
                acc[j] += xv.x * wv.x + xv.y * wv.y + xv.z * wv.z + xv.w * wv.w;
            }
        }
#pragma unroll
        for (int j = 0; j < H; j++) {
#pragma unroll
            for (int off = 16; off; off >>= 1)
                acc[j] += __shfl_xor_sync(0xffffffffu, acc[j], off);
        }
        if (lane == 0) {
#pragma unroll
            for (int j = 0; j < H; j++) {
                float yv = acc[j] + __ldg(b1 + j);
                g_y[n * H + j] = yv;
                ls[j] += (double)yv;
                lq[j] += (double)yv * (double)yv;
            }
        }
    }
    if (lane == 0) {
#pragma unroll
        for (int j = 0; j < H; j++) {
            atomicAdd(&g_s1[j], ls[j]);
            atomicAdd(&g_sq1[j], lq[j]);
        }
    }
}

// ---------------- kernel A2: BN1 affine params + zero-cell bias ----------------
__global__ void k_bnparams(const float* __restrict__ g1, const float* __restrict__ be1,
                           const float* __restrict__ b_ih, const float* __restrict__ b_hh) {
    int t = threadIdx.x;
    if (t < H) {
        double m   = g_s1[t] / (double)NROWS;
        double var = g_sq1[t] / (double)NROWS - m * m;
        float inv  = (float)(1.0 / sqrt(var + 1e-5));
        float sc   = inv * __ldg(g1 + t);
        g_scale1[t] = sc;
        g_shift1[t] = __ldg(be1 + t) - (float)m * sc;
    }
    if (t < G4) g_bias0[t] = __ldg(b_ih + t) + __ldg(b_hh + t);
}

// ---------------- kernel B: u[n,r] = b_ih[r]+b_hh[r] + W_ih[r,:] . x1[n,:]; meta ----------------
__global__ void k_u(const float* __restrict__ W_ih,
                    const float* __restrict__ b_ih, const float* __restrict__ b_hh,
                    const int* __restrict__ zero_pad, const int* __restrict__ broad_id) {
    int tid = blockIdx.x * blockDim.x + threadIdx.x;
    if (tid >= NROWS * G4) return;
    int n = tid / G4;
    int r = tid % G4;
    float acc = __ldg(b_ih + r) + __ldg(b_hh + r);
#pragma unroll
    for (int j = 0; j < H; j++) {
        float x1 = g_y[n * H + j] * g_scale1[j] + g_shift1[j];
        acc += __ldg(W_ih + r * H + j) * x1;
    }
    g_u[tid] = acc;
    if (r == 0) {
        int zp = __ldg(zero_pad + n);
        if (zp < 0) zp = 0;
        if (zp > 3) zp = 3;
        int bnd = (n == NROWS - 1) || (__ldg(broad_id + n + 1) != __ldg(broad_id + n));
        g_meta[n] = zp | (bnd << 8);
    }
}

// ---------------- scan math helpers ----------------
__device__ __forceinline__ float sigf(float x) {
    // safe for all x: e->inf => 1/inf = 0 ; e->0 => 1
    float e = __expf(-x);
    return __fdividef(1.f, 1.f + e);
}
__device__ __forceinline__ float tanhfast(float x) {
    // overflow-safe: use |x| so exp never overflows
    float a = fabsf(x);
    float e = __expf(-2.f * a);
    float r = __fdividef(1.f - e, 1.f + e);
    return copysignf(r, x);
}

// ---------------- kernel C: the sequential scan (single warp) ----------------
__global__ void k_scan(const float* __restrict__ W_hh) {
    int j  = threadIdx.x;
    int lj = (j < H) ? j : 0;

    // W_hh rows for this lane's 4 gates (torch order i,f,g,o)
    float wi[H], wf[H], wg[H], wo[H];
#pragma unroll
    for (int k = 0; k < H; k++) {
        wi[k] = __ldg(W_hh + (0 * H + lj) * H + k);
        wf[k] = __ldg(W_hh + (1 * H + lj) * H + k);
        wg[k] = __ldg(W_hh + (2 * H + lj) * H + k);
        wo[k] = __ldg(W_hh + (3 * H + lj) * H + k);
    }
    float bz0 = g_bias0[0 * H + lj], bz1 = g_bias0[1 * H + lj];
    float bz2 = g_bias0[2 * H + lj], bz3 = g_bias0[3 * H + lj];

    float hv[H];
#pragma unroll
    for (int k = 0; k < H; k++) hv[k] = 0.f;
    float c = 0.f, sh = 0.f, sc = 0.f, cnt = 0.f;
    double s1 = 0.0, s2 = 0.0;

    // prefetch t = 0
    int   cmeta = g_meta[0];
    float cu0 = __ldg(g_u + 0 * H + lj);
    float cu1 = __ldg(g_u + 1 * H + lj);
    float cu2 = __ldg(g_u + 2 * H + lj);
    float cu3 = __ldg(g_u + 3 * H + lj);

    for (int t = 0; t < NROWS; t++) {
        // prefetch next step (independent of the recurrence chain)
        int nmeta = 0;
        float nu0 = 0.f, nu1 = 0.f, nu2 = 0.f, nu3 = 0.f;
        if (t + 1 < NROWS) {
            const float* up = g_u + (size_t)(t + 1) * G4;
            nmeta = g_meta[t + 1];
            nu0 = __ldg(up + 0 * H + lj);
            nu1 = __ldg(up + 1 * H + lj);
            nu2 = __ldg(up + 2 * H + lj);
            nu3 = __ldg(up + 3 * H + lj);
        }

        int zp = cmeta & 0xff;
        // zero-input cells (advance carry)
        for (int k = 0; k < zp; k++) {
            float pi = bz0, pf = bz1, pg = bz2, po = bz3;
#pragma unroll
            for (int q = 0; q < H; q++) {
                pi += wi[q] * hv[q];
                pf += wf[q] * hv[q];
                pg += wg[q] * hv[q];
                po += wo[q] * hv[q];
            }
            float ig = sigf(pi), fg = sigf(pf), gg = tanhfast(pg), og = sigf(po);
            c = fg * c + ig * gg;
            float hn = og * tanhfast(c);
#pragma unroll
            for (int q = 0; q < H; q++) hv[q] = __shfl_sync(0xffffffffu, hn, q);
        }

        // input cell (does NOT advance carry; feeds sums/output only)
        {
            float pi = cu0, pf = cu1, pg = cu2, po = cu3;
#pragma unroll
            for (int q = 0; q < H; q++) {
                pi += wi[q] * hv[q];
                pf += wf[q] * hv[q];
                pg += wg[q] * hv[q];
                po += wo[q] * hv[q];
            }
            float ig = sigf(pi), fg = sigf(pf), gg = tanhfast(pg), og = sigf(po);
            float ct = fg * c + ig * gg;
            float ht = og * tanhfast(ct);

            if (j < H) g_outs[t * H + j] = ht;
            s1 += (double)ht;
            s2 = fma((double)ht, (double)ht, s2);
            sh += ht; sc += ct; cnt += 1.f;

            if (cmeta & 0x100) {  // group boundary: carry = group means, reset sums
                float invc = __fdividef(1.f, cnt);
                float hn   = sh * invc;
                c          = sc * invc;
                sh = 0.f; sc = 0.f; cnt = 0.f;
#pragma unroll
                for (int q = 0; q < H; q++) hv[q] = __shfl_sync(0xffffffffu, hn, q);
            }
        }

        cmeta = nmeta; cu0 = nu0; cu1 = nu1; cu2 = nu2; cu3 = nu3;
    }

    if (j < H) { g_s2[j] = s1; g_s2[H + j] = s2; }
}

// ---------------- kernel D: fold BN2 + W2 + b2 into alpha/cst ----------------
__global__ void k_post(const float* __restrict__ g2, const float* __restrict__ be2,
                       const float* __restrict__ W2, const float* __restrict__ b2) {
    if (threadIdx.x == 0) {
        float cst = __ldg(b2);
#pragma unroll
        for (int jj = 0; jj < H; jj++) {
            double m   = g_s2[jj] / (double)NROWS;
            double var = g_s2[H + jj] / (double)NROWS - m * m;
            float inv  = (float)(1.0 / sqrt(var + 1e-5));
            float a    = __ldg(W2 + jj) * __ldg(g2 + jj) * inv;
            g_alpha[jj] = a;
            cst += __ldg(W2 + jj) * __ldg(be2 + jj) - (float)m * a;
        }
        g_cst[0] = cst;
    }
}

// ---------------- kernel E: out = tanh(outs . alpha + cst) ----------------
__global__ void k_final(float* __restrict__ out) {
    int n = blockIdx.x * blockDim.x + threadIdx.x;
    if (n >= NROWS) return;
    float acc = g_cst[0];
#pragma unroll
    for (int jj = 0; jj < H; jj++)
        acc += g_outs[n * H + jj] * g_alpha[jj];
    out[n] = tanhf(acc);
}

// ---------------- launch ----------------
extern "C" void kernel_launch(void* const* d_in, const int* in_sizes, int n_in,
                              void* d_out, int out_size) {
    const float* x        = (const float*)d_in[0];
    const int*   zero_pad = (const int*)d_in[1];
    const int*   broad_id = (const int*)d_in[2];
    const float* W1       = (const float*)d_in[3];
    const float* b1       = (const float*)d_in[4];
    const float* g1       = (const float*)d_in[5];
    const float* be1      = (const float*)d_in[6];
    const float* W_ih     = (const float*)d_in[7];
    const float* W_hh     = (const float*)d_in[8];
    const float* b_ih     = (const float*)d_in[9];
    const float* b_hh     = (const float*)d_in[10];
    const float* g2       = (const float*)d_in[11];
    const float* be2      = (const float*)d_in[12];
    const float* W2       = (const float*)d_in[13];
    const float* b2       = (const float*)d_in[14];
    float* out = (float*)d_out;

    k_init<<<1, 32>>>();
    k_proj<<<512, 256>>>(x, W1, b1);
    k_bnparams<<<1, 64>>>(g1, be1, b_ih, b_hh);
    k_u<<<(NROWS * G4) / 256, 256>>>(W_ih, b_ih, b_hh, zero_pad, broad_id);
    k_scan<<<1, 32>>>(W_hh);
    k_post<<<1, 32>>>(g2, be2, W2, b2);
    k_final<<<NROWS / 256, 256>>>(out);
}

// round 2
// speedup vs baseline: 1.7564x; 1.7564x over previous
#include <cuda_runtime.h>
#include <math.h>

#define NROWS 65536
#define D 512
#define H 10
#define G4 40

// ---------------- scratch (static device globals; no allocation) ----------------
__device__ float  g_y[NROWS * H];          // layer-1 pre-BN activations
__device__ float  g_u[(NROWS + 2) * G4];   // precomputed input-gate bases (i,f,o rows pre-scaled by 0.5)
__device__ float  g_outs[NROWS * H];       // scan outputs (ht)
__device__ int    g_meta[NROWS + 2];       // zp | (bnd<<8)
__device__ double g_s1[H], g_sq1[H];       // BN1 sums (atomically accumulated)
__device__ float  g_scale1[H], g_shift1[H];
__device__ float  g_bias0[G4];             // 0.5*(b_ih+b_hh) for i,f,o ; 1.0* for g
__device__ double g_s2[2 * H];             // BN2 sums (post-pass reduction)
__device__ float  g_alpha[H];
__device__ float  g_cst[1];

// ---------------- init: zero the atomically-accumulated stats ----------------
__global__ void k_init() {
    int t = threadIdx.x;
    if (t < H)     { g_s1[t] = 0.0; g_sq1[t] = 0.0; }
    if (t < 2 * H) { g_s2[t] = 0.0; }
}

// ---------------- kernel A: y = x @ W1^T + b1, accumulate BN1 sums ----------------
__global__ void k_proj(const float* __restrict__ x,
                       const float* __restrict__ W1,
                       const float* __restrict__ b1) {
    int gtid  = blockIdx.x * blockDim.x + threadIdx.x;
    int w     = gtid >> 5;
    int lane  = threadIdx.x & 31;
    int nwarp = (gridDim.x * blockDim.x) >> 5;

    double ls[H], lq[H];
#pragma unroll
    for (int j = 0; j < H; j++) { ls[j] = 0.0; lq[j] = 0.0; }

    const float4* x4  = reinterpret_cast<const float4*>(x);
    const float4* W14 = reinterpret_cast<const float4*>(W1);

    for (int n = w; n < NROWS; n += nwarp) {
        float acc[H];
#pragma unroll
        for (int j = 0; j < H; j++) acc[j] = 0.f;
        const float4* xr = x4 + (size_t)n * (D / 4);
#pragma unroll
        for (int it = 0; it < D / 4 / 32; it++) {
            float4 xv = __ldg(xr + lane + 32 * it);
#pragma unroll
            for (int j = 0; j < H; j++) {
                float4 wv = __ldg(W14 + j * (D / 4) + lane + 32 * it);
                acc[j] += xv.x * wv.x + xv.y * wv.y + xv.z * wv.z + xv.w * wv.w;
            }
        }
#pragma unroll
        for (int j = 0; j < H; j++) {
#pragma unroll
            for (int off = 16; off; off >>= 1)
                acc[j] += __shfl_xor_sync(0xffffffffu, acc[j], off);
        }
        if (lane == 0) {
#pragma unroll
            for (int j = 0; j < H; j++) {
                float yv = acc[j] + __ldg(b1 + j);
                g_y[n * H + j] = yv;
                ls[j] += (double)yv;
                lq[j] += (double)yv * (double)yv;
            }
        }
    }
    if (lane == 0) {
#pragma unroll
        for (int j = 0; j < H; j++) {
            atomicAdd(&g_s1[j], ls[j]);
            atomicAdd(&g_sq1[j], lq[j]);
        }
    }
}

// ---------------- kernel A2: BN1 affine params + zero-cell bias (pre-scaled) ----------------
__global__ void k_bnparams(const float* __restrict__ g1, const float* __restrict__ be1,
                           const float* __restrict__ b_ih, const float* __restrict__ b_hh) {
    int t = threadIdx.x;
    if (t < H) {
        double m   = g_s1[t] / (double)NROWS;
        double var = g_sq1[t] / (double)NROWS - m * m;
        float inv  = (float)(1.0 / sqrt(var + 1e-5));
        float sc   = inv * __ldg(g1 + t);
        g_scale1[t] = sc;
        g_shift1[t] = __ldg(be1 + t) - (float)m * sc;
    }
    if (t < G4) {
        int gate = t / H;                       // 0:i 1:f 2:g 3:o
        float s  = (gate == 2) ? 1.0f : 0.5f;   // fold sigmoid's x/2
        g_bias0[t] = s * (__ldg(b_ih + t) + __ldg(b_hh + t));
    }
}

// ---------------- kernel B: u[n,r] = scale_r*(b_ih+b_hh + W_ih[r,:].x1[n,:]) ----------------
__global__ void k_u(const float* __restrict__ W_ih,
                    const float* __restrict__ b_ih, const float* __restrict__ b_hh,
                    const int* __restrict__ zero_pad, const int* __restrict__ broad_id) {
    int tid = blockIdx.x * blockDim.x + threadIdx.x;
    if (tid >= NROWS * G4) return;
    int n = tid / G4;
    int r = tid % G4;
    float acc = __ldg(b_ih + r) + __ldg(b_hh + r);
#pragma unroll
    for (int j = 0; j < H; j++) {
        float x1 = g_y[n * H + j] * g_scale1[j] + g_shift1[j];
        acc += __ldg(W_ih + r * H + j) * x1;
    }
    int gate = r / H;
    if (gate != 2) acc *= 0.5f;                 // fold sigmoid's x/2 for i,f,o
    g_u[tid] = acc;
    if (r == 0) {
        int zp = __ldg(zero_pad + n);
        if (zp < 0) zp = 0;
        if (zp > 3) zp = 3;
        int bnd = (n == NROWS - 1) || (__ldg(broad_id + n + 1) != __ldg(broad_id + n));
        g_meta[n] = zp | (bnd << 8);
        if (n == 0) {                           // pad tail so prefetch never branches
            g_meta[NROWS] = 0; g_meta[NROWS + 1] = 0;
#pragma unroll
            for (int q = 0; q < 2 * G4; q++) g_u[NROWS * G4 + q] = 0.f;
        }
    }
}

// ---------------- scan math: hardware tanh ----------------
__device__ __forceinline__ float tanhapx(float x) {
    float y;
    asm("tanh.approx.f32 %0, %1;" : "=f"(y) : "f"(x));
    return y;
}
// sigmoid with pre-halved argument p = x/2:  sigma(x) = 0.5 + 0.5*tanh(p)
__device__ __forceinline__ float sig_h(float p) {
    return fmaf(tanhapx(p), 0.5f, 0.5f);
}

// ---------------- kernel C: the sequential scan (single warp) ----------------
__global__ void k_scan(const float* __restrict__ W_hh) {
    int j  = threadIdx.x;
    int lj = (j < H) ? j : 0;

    // W_hh rows for this lane's 4 gates; i,f,o rows folded by 0.5 for sig_h
    float wi[H], wf[H], wg[H], wo[H];
#pragma unroll
    for (int k = 0; k < H; k++) {
        wi[k] = 0.5f * __ldg(W_hh + (0 * H + lj) * H + k);
        wf[k] = 0.5f * __ldg(W_hh + (1 * H + lj) * H + k);
        wg[k] =        __ldg(W_hh + (2 * H + lj) * H + k);
        wo[k] = 0.5f * __ldg(W_hh + (3 * H + lj) * H + k);
    }
    float bz0 = g_bias0[0 * H + lj], bz1 = g_bias0[1 * H + lj];
    float bz2 = g_bias0[2 * H + lj], bz3 = g_bias0[3 * H + lj];

    float hv[H];
#pragma unroll
    for (int k = 0; k < H; k++) hv[k] = 0.f;
    float c = 0.f, sh = 0.f, sc = 0.f, cnt = 0.f;

    // prefetch t = 0 and t = 1 (arrays padded; no bounds branches)
    int   m0 = g_meta[0], m1 = g_meta[1];
    float a0 = __ldg(g_u + 0 * H + lj);
    float a1 = __ldg(g_u + 1 * H + lj);
    float a2 = __ldg(g_u + 2 * H + lj);
    float a3 = __ldg(g_u + 3 * H + lj);
    float p0 = __ldg(g_u + G4 + 0 * H + lj);
    float p1 = __ldg(g_u + G4 + 1 * H + lj);
    float p2 = __ldg(g_u + G4 + 2 * H + lj);
    float p3 = __ldg(g_u + G4 + 3 * H + lj);

    for (int t = 0; t < NROWS; t++) {
        // prefetch step t+2 (independent of the recurrence chain)
        const float* up = g_u + (size_t)(t + 2) * G4;
        int   m2 = g_meta[t + 2];
        float q0 = __ldg(up + 0 * H + lj);
        float q1 = __ldg(up + 1 * H + lj);
        float q2 = __ldg(up + 2 * H + lj);
        float q3 = __ldg(up + 3 * H + lj);

        int zp = m0 & 0xff;
        // zero-input cells (advance carry)
        for (int k = 0; k < zp; k++) {
            float pi = bz0, pf = bz1, pg = bz2, po = bz3;
#pragma unroll
            for (int q = 0; q < H; q++) {
                pi += wi[q] * hv[q];
                pf += wf[q] * hv[q];
                pg += wg[q] * hv[q];
                po += wo[q] * hv[q];
            }
            float ig = sig_h(pi), fg = sig_h(pf), gg = tanhapx(pg), og = sig_h(po);
            c = fmaf(fg, c, ig * gg);
            float hn = og * tanhapx(c);
#pragma unroll
            for (int q = 0; q < H; q++) hv[q] = __shfl_sync(0xffffffffu, hn, q);
        }

        // input cell (does NOT advance carry; feeds sums/output only)
        {
            float pi = a0, pf = a1, pg = a2, po = a3;
#pragma unroll
            for (int q = 0; q < H; q++) {
                pi += wi[q] * hv[q];
                pf += wf[q] * hv[q];
                pg += wg[q] * hv[q];
                po += wo[q] * hv[q];
            }
            float ig = sig_h(pi), fg = sig_h(pf), gg = tanhapx(pg), og = sig_h(po);
            float ct = fmaf(fg, c, ig * gg);
            float ht = og * tanhapx(ct);

            if (j < H) g_outs[t * H + j] = ht;
            sh += ht; sc += ct; cnt += 1.f;

            if (m0 & 0x100) {  // group boundary: carry = group means, reset sums
                float invc = __fdividef(1.f, cnt);
                float hn   = sh * invc;
                c          = sc * invc;
                sh = 0.f; sc = 0.f; cnt = 0.f;
#pragma unroll
                for (int q = 0; q < H; q++) hv[q] = __shfl_sync(0xffffffffu, hn, q);
            }
        }

        m0 = m1; a0 = p0; a1 = p1; a2 = p2; a3 = p3;
        m1 = m2; p0 = q0; p1 = q1; p2 = q2; p3 = q3;
    }
}

// ---------------- kernel C2: BN2 sums over g_outs (parallel post-pass) ----------------
__global__ void k_stats() {
    int gtid  = blockIdx.x * blockDim.x + threadIdx.x;
    int w     = gtid >> 5;
    int lane  = threadIdx.x & 31;
    int nwarp = (gridDim.x * blockDim.x) >> 5;
    if (lane >= H) return;
    double s = 0.0, q = 0.0;
    for (int n = w; n < NROWS; n += nwarp) {
        double v = (double)g_outs[n * H + lane];
        s += v;
        q += v * v;
    }
    atomicAdd(&g_s2[lane], s);
    atomicAdd(&g_s2[H + lane], q);
}

// ---------------- kernel D: fold BN2 + W2 + b2 into alpha/cst ----------------
__global__ void k_post(const float* __restrict__ g2, const float* __restrict__ be2,
                       const float* __restrict__ W2, const float* __restrict__ b2) {
    if (threadIdx.x == 0) {
        float cst = __ldg(b2);
#pragma unroll
        for (int jj = 0; jj < H; jj++) {
            double m   = g_s2[jj] / (double)NROWS;
            double var = g_s2[H + jj] / (double)NROWS - m * m;
            float inv  = (float)(1.0 / sqrt(var + 1e-5));
            float a    = __ldg(W2 + jj) * __ldg(g2 + jj) * inv;
            g_alpha[jj] = a;
            cst += __ldg(W2 + jj) * __ldg(be2 + jj) - (float)m * a;
        }
        g_cst[0] = cst;
    }
}

// ---------------- kernel E: out = tanh(outs . alpha + cst) ----------------
__global__ void k_final(float* __restrict__ out) {
    int n = blockIdx.x * blockDim.x + threadIdx.x;
    if (n >= NROWS) return;
    float acc = g_cst[0];
#pragma unroll
    for (int jj = 0; jj < H; jj++)
        acc += g_outs[n * H + jj] * g_alpha[jj];
    out[n] = tanhf(acc);
}

// ---------------- launch ----------------
extern "C" void kernel_launch(void* const* d_in, const int* in_sizes, int n_in,
                              void* d_out, int out_size) {
    const float* x        = (const float*)d_in[0];
    const int*   zero_pad = (const int*)d_in[1];
    const int*   broad_id = (const int*)d_in[2];
    const float* W1       = (const float*)d_in[3];
    const float* b1       = (const float*)d_in[4];
    const float* g1       = (const float*)d_in[5];
    const float* be1      = (const float*)d_in[6];
    const float* W_ih     = (const float*)d_in[7];
    const float* W_hh     = (const float*)d_in[8];
    const float* b_ih     = (const float*)d_in[9];
    const float* b_hh     = (const float*)d_in[10];
    const float* g2       = (const float*)d_in[11];
    const float* be2      = (const float*)d_in[12];
    const float* W2       = (const float*)d_in[13];
    const float* b2       = (const float*)d_in[14];
    float* out = (float*)d_out;

    k_init<<<1, 32>>>();
    k_proj<<<512, 256>>>(x, W1, b1);
    k_bnparams<<<1, 64>>>(g1, be1, b_ih, b_hh);
    k_u<<<(NROWS * G4) / 256, 256>>>(W_ih, b_ih, b_hh, zero_pad, broad_id);
    k_scan<<<1, 32>>>(W_hh);
    k_stats<<<128, 256>>>();
    k_post<<<1, 32>>>(g2, be2, W2, b2);
    k_final<<<NROWS / 256, 256>>>(out);
}